// round 8
// baseline (speedup 1.0000x reference)
#include <cuda_runtime.h>
#include <cuda_bf16.h>
#include <math.h>
#include <cstdint>

#define BB 16
#define NT 16

// ---------------- persistent scratch (device globals; no allocation) -------
__device__ float g_h [16*64*1024];     // attended h (recurrent carry)
__device__ float g_hg[16*64*1024];     // pre-attention h (gate output)
__device__ float g_c [16*64*1024];     // cell state
__device__ float g_q [16*16*1024];
__device__ float g_k [16*16*1024];
__device__ float g_v [16*64*1024];
__device__ float g_conv[16*256*1024];  // conv output (B,256,32,32), pre-bias
__device__ float g_P [16*1024*1024];   // attention probs (64 MB)
// bf16 hi/lo split conv weights in mma-fragment-linear order:
// [gate][c0(18)][split(2)][ni(8)][ki(4)][lane(32)][slot(2)] as u32(bf16x2)
__device__ uint32_t g_Wfrag[294912];

// ---------------- init: zero h and c ---------------------------------------
__global__ void k_init()
{
    int i = blockIdx.x * 256 + threadIdx.x;
    g_h[i] = 0.f;
    g_c[i] = 0.f;
}

__device__ __forceinline__ float sigf(float x) { return 1.f / (1.f + __expf(-x)); }
__device__ __forceinline__ float tanh_fast(float x)
{
    return __fdividef(2.f, 1.f + __expf(-2.f * x)) - 1.f;
}
__device__ __forceinline__ uint32_t pack_bf16(float a, float b)
{
    __nv_bfloat162 h2 = __floats2bfloat162_rn(a, b);
    return *reinterpret_cast<uint32_t*>(&h2);
}
__device__ __forceinline__ float bf16_lo(float a)
{
    return a - __bfloat162float(__float2bfloat16(a));
}

// ---------------- weight prep: split + fragment-linear layout --------------
__global__ void k_prepw(const float* __restrict__ Wc)
{
    int idx   = blockIdx.x * 256 + threadIdx.x;   // 294912
    int inner = idx & 4095;
    int outer = idx >> 12;                        // 0..71
    int c0    = outer % 18;
    int gate  = outer / 18;
    int s     = inner & 1;
    int lane  = (inner >> 1) & 31;
    int ki    = (inner >> 6) & 3;
    int ni    = (inner >> 8) & 7;
    int sp    = (inner >> 11) & 1;

    int g = lane >> 2, tt = lane & 3;
    int n_global = gate * 64 + ni * 8 + g;
    int k0 = c0 * 64 + ki * 16 + 2 * tt + 8 * s;

    float w0, w1;
    {
        int ci = k0 / 9, r = k0 - ci * 9;
        w0 = Wc[(n_global * 128 + ci) * 9 + r];
        int k1 = k0 + 1;
        ci = k1 / 9; r = k1 - ci * 9;
        w1 = Wc[(n_global * 128 + ci) * 9 + r];
    }
    if (sp == 1) { w0 = bf16_lo(w0); w1 = bf16_lo(w1); }
    g_Wfrag[idx] = pack_bf16(w0, w1);
}

// ---------------- conv via mma.sync bf16 (HMMA fallback path) --------------
__device__ __forceinline__ void mma_bf16(float* c, uint4 a, uint2 b)
{
    asm volatile(
        "mma.sync.aligned.m16n8k16.row.col.f32.bf16.bf16.f32 "
        "{%0,%1,%2,%3}, {%4,%5,%6,%7}, {%8,%9}, {%0,%1,%2,%3};"
        : "+f"(c[0]), "+f"(c[1]), "+f"(c[2]), "+f"(c[3])
        : "r"(a.x), "r"(a.y), "r"(a.z), "r"(a.w), "r"(b.x), "r"(b.y));
}

__global__ void __launch_bounds__(256, 2) k_conv_mma(
    const float* __restrict__ X, int t)
{
    __shared__ uint32_t sm_u[8448];               // 33 KB
    uint32_t* A_s  = sm_u;
    uint32_t* Bh_s = sm_u + 4096;
    uint32_t* Bl_s = sm_u + 6144;

    const int tid  = threadIdx.x;
    const int wid  = tid >> 5;
    const int lane = tid & 31;
    const int mt   = blockIdx.x;
    const int b    = blockIdx.y;
    const int gate = blockIdx.z;
    const int n0   = gate * 64;
    const int wm   = wid >> 1;
    const int wn   = wid & 1;
    const int g    = lane >> 2, tt = lane & 3;

    const float* Xb = X + (b * 64 * 16 + t) * 1024;
    const float* Hb = g_h + b * 64 * 1024;

    float acc[2][4][4];
    #pragma unroll
    for (int im = 0; im < 2; ++im)
        #pragma unroll
        for (int in = 0; in < 4; ++in)
            #pragma unroll
            for (int q = 0; q < 4; ++q) acc[im][in][q] = 0.f;

    float av[32];
    const uint4* A4  = reinterpret_cast<const uint4*>(A_s);
    const uint2* Bh2 = reinterpret_cast<const uint2*>(Bh_s);
    const uint2* Bl2 = reinterpret_cast<const uint2*>(Bl_s);

    for (int c0 = 0; c0 < 18; ++c0) {
        #pragma unroll
        for (int j = 0; j < 16; ++j) {
            int slot = j * 256 + tid;
            int s  = slot & 3;
            int ln = (slot >> 2) & 31;
            int ki = (slot >> 7) & 3;
            int mi = slot >> 9;
            int gg = ln >> 2, t4 = ln & 3;
            int m  = mi * 16 + gg + 8 * (s & 1);
            int kb = c0 * 64 + ki * 16 + 2 * t4 + 8 * (s >> 1);
            int pix = mt * 128 + m;
            int py = pix >> 5, px = pix & 31;
            float a0 = 0.f, a1 = 0.f;
            #pragma unroll
            for (int h = 0; h < 2; ++h) {
                int kg = kb + h;
                int ci = kg / 9, r = kg - ci * 9;
                int dy = r / 3 - 1, dx = r - (r / 3) * 3 - 1;
                int ys = py + dy, xs = px + dx;
                float a = 0.f;
                if ((unsigned)ys < 32u && (unsigned)xs < 32u) {
                    int sp2 = ys * 32 + xs;
                    a = (ci < 64) ? Xb[ci * 16384 + sp2]
                                  : Hb[(ci - 64) * 1024 + sp2];
                }
                if (h == 0) a0 = a; else a1 = a;
            }
            av[2 * j] = a0; av[2 * j + 1] = a1;
            A_s[slot] = pack_bf16(a0, a1);
        }
        {
            const uint4* src = reinterpret_cast<const uint4*>(
                g_Wfrag + (gate * 18 + c0) * 4096);
            uint4* dh = reinterpret_cast<uint4*>(Bh_s);
            uint4* dl = reinterpret_cast<uint4*>(Bl_s);
            dh[tid]       = src[tid];
            dh[tid + 256] = src[tid + 256];
            dl[tid]       = src[tid + 512];
            dl[tid + 256] = src[tid + 768];
        }
        __syncthreads();

        #pragma unroll
        for (int ki = 0; ki < 4; ++ki) {
            uint4 af0 = A4[((wm * 2    ) * 4 + ki) * 32 + lane];
            uint4 af1 = A4[((wm * 2 + 1) * 4 + ki) * 32 + lane];
            #pragma unroll
            for (int in = 0; in < 4; ++in) {
                int ni = wn * 4 + in;
                uint2 bh = Bh2[(ni * 4 + ki) * 32 + lane];
                uint2 bl = Bl2[(ni * 4 + ki) * 32 + lane];
                mma_bf16(acc[0][in], af0, bh);
                mma_bf16(acc[1][in], af1, bh);
                mma_bf16(acc[0][in], af0, bl);
                mma_bf16(acc[1][in], af1, bl);
            }
        }
        __syncthreads();

        #pragma unroll
        for (int j = 0; j < 16; ++j) {
            int slot = j * 256 + tid;
            A_s[slot] = pack_bf16(bf16_lo(av[2 * j]), bf16_lo(av[2 * j + 1]));
        }
        __syncthreads();

        #pragma unroll
        for (int ki = 0; ki < 4; ++ki) {
            uint4 af0 = A4[((wm * 2    ) * 4 + ki) * 32 + lane];
            uint4 af1 = A4[((wm * 2 + 1) * 4 + ki) * 32 + lane];
            #pragma unroll
            for (int in = 0; in < 4; ++in) {
                int ni = wn * 4 + in;
                uint2 bh = Bh2[(ni * 4 + ki) * 32 + lane];
                mma_bf16(acc[0][in], af0, bh);
                mma_bf16(acc[1][in], af1, bh);
            }
        }
        __syncthreads();
    }

    float* out_s = reinterpret_cast<float*>(sm_u);
    #pragma unroll
    for (int im = 0; im < 2; ++im) {
        int mi = wm * 2 + im;
        int m  = mi * 16 + g;
        #pragma unroll
        for (int in = 0; in < 4; ++in) {
            int ni = wn * 4 + in;
            int n  = ni * 8 + 2 * tt;
            out_s[ n      * 132 + m    ] = acc[im][in][0];
            out_s[(n + 1) * 132 + m    ] = acc[im][in][1];
            out_s[ n      * 132 + m + 8] = acc[im][in][2];
            out_s[(n + 1) * 132 + m + 8] = acc[im][in][3];
        }
    }
    __syncthreads();
    #pragma unroll
    for (int j = 0; j < 32; ++j) {
        int idx = j * 256 + tid;
        int n = idx >> 7, m = idx & 127;
        g_conv[(b * 256 + n0 + n) * 1024 + mt * 128 + m] = out_s[n * 132 + m];
    }
}

// ---------------- ConvLSTM gating (elementwise, peephole; adds bias) -------
__global__ void k_gate(const float* __restrict__ bc,
                       const float* __restrict__ Wci,
                       const float* __restrict__ Wcf,
                       const float* __restrict__ Wco)
{
    int idx = blockIdx.x * 256 + threadIdx.x;
    int b   = idx >> 16;
    int c   = (idx >> 10) & 63;
    int pos = idx & 1023;
    int cb  = (b * 256 + c) * 1024 + pos;

    float ic = g_conv[cb]              + bc[c];
    float fc = g_conv[cb + 64 * 1024]  + bc[64 + c];
    float gc = g_conv[cb + 128 * 1024] + bc[128 + c];
    float oc = g_conv[cb + 192 * 1024] + bc[192 + c];
    float cp = g_c[idx];
    int   wp = c * 1024 + pos;

    float i  = sigf(ic + Wci[wp] * cp);
    float f  = sigf(fc + Wcf[wp] * cp);
    float nc = f * cp + i * tanh_fast(gc);
    float o  = sigf(oc + Wco[wp] * nc);
    g_c[idx]  = nc;
    g_hg[idx] = o * tanh_fast(nc);
}

// ---------------- q,k,v 1x1 convs: 96 output ch from 64 --------------------
__global__ void k_qkv(const float* __restrict__ qw, const float* __restrict__ qb,
                      const float* __restrict__ kw, const float* __restrict__ kb,
                      const float* __restrict__ vw, const float* __restrict__ vb)
{
    __shared__ float h_s[32 * 256];
    __shared__ float w_s[8 * 64];

    const int p0  = blockIdx.x * 256;
    const int oc0 = blockIdx.y * 8;
    const int b   = blockIdx.z;
    const int tid = threadIdx.x;

    for (int i = tid; i < 512; i += 256) {
        int j = i >> 6; int c = i & 63; int oc = oc0 + j;
        w_s[i] = (oc < 16) ? qw[oc * 64 + c]
               : (oc < 32) ? kw[(oc - 16) * 64 + c]
                           : vw[(oc - 32) * 64 + c];
    }

    float acc[8];
    #pragma unroll
    for (int j = 0; j < 8; ++j) {
        int oc = oc0 + j;
        acc[j] = (oc < 16) ? qb[oc] : (oc < 32) ? kb[oc - 16] : vb[oc - 32];
    }

    for (int chh = 0; chh < 2; ++chh) {
        __syncthreads();
        for (int i = tid; i < 8192; i += 256) {
            int c = i >> 8; int j = i & 255;
            h_s[i] = g_hg[(b * 64 + chh * 32 + c) * 1024 + p0 + j];
        }
        __syncthreads();
        #pragma unroll 8
        for (int c = 0; c < 32; ++c) {
            float hv = h_s[c * 256 + tid];
            #pragma unroll
            for (int j = 0; j < 8; ++j)
                acc[j] += w_s[j * 64 + chh * 32 + c] * hv;
        }
    }

    int pos = p0 + tid;
    #pragma unroll
    for (int j = 0; j < 8; ++j) {
        int oc = oc0 + j;
        if (oc < 16)      g_q[(b * 16 + oc) * 1024 + pos]        = acc[j];
        else if (oc < 32) g_k[(b * 16 + (oc - 16)) * 1024 + pos] = acc[j];
        else              g_v[(b * 64 + (oc - 32)) * 1024 + pos] = acc[j];
    }
}

// ---------------- scores + softmax fused: P[b][n][m] (R1 design) -----------
// grid (64 row-groups, 16 batch), 256 threads. Warp = 2 rows, scores in regs.
__global__ void __launch_bounds__(256, 2) k_scores()
{
    __shared__ float k_s[16 * 512];   // 32 KB, half of k's m-range at a time
    const int b    = blockIdx.y;
    const int r0   = blockIdx.x * 16 + ((threadIdx.x >> 5) << 1);
    const int lane = threadIdx.x & 31;

    float q0[16], q1[16];
    #pragma unroll
    for (int c = 0; c < 16; ++c) {
        q0[c] = g_q[(b * 16 + c) * 1024 + r0];
        q1[c] = g_q[(b * 16 + c) * 1024 + r0 + 1];
    }

    float s0[32], s1[32];
    for (int chh = 0; chh < 2; ++chh) {
        __syncthreads();
        for (int i = threadIdx.x; i < 8192; i += 256) {
            int c = i >> 9; int mm = i & 511;
            k_s[i] = g_k[(b * 16 + c) * 1024 + chh * 512 + mm];
        }
        __syncthreads();
        #pragma unroll
        for (int jj = 0; jj < 16; ++jj) {
            int j  = chh * 16 + jj;
            int mm = jj * 32 + lane;
            float a = 0.f, bb2 = 0.f;
            #pragma unroll
            for (int c = 0; c < 16; ++c) {
                float kv = k_s[c * 512 + mm];
                a   += q0[c] * kv;
                bb2 += q1[c] * kv;
            }
            s0[j] = a; s1[j] = bb2;
        }
    }

    float m0 = -1e30f, m1 = -1e30f;
    #pragma unroll
    for (int j = 0; j < 32; ++j) { m0 = fmaxf(m0, s0[j]); m1 = fmaxf(m1, s1[j]); }
    #pragma unroll
    for (int o = 16; o > 0; o >>= 1) {
        m0 = fmaxf(m0, __shfl_xor_sync(0xffffffffu, m0, o));
        m1 = fmaxf(m1, __shfl_xor_sync(0xffffffffu, m1, o));
    }
    float sum0 = 0.f, sum1 = 0.f;
    #pragma unroll
    for (int j = 0; j < 32; ++j) {
        s0[j] = __expf(s0[j] - m0); sum0 += s0[j];
        s1[j] = __expf(s1[j] - m1); sum1 += s1[j];
    }
    #pragma unroll
    for (int o = 16; o > 0; o >>= 1) {
        sum0 += __shfl_xor_sync(0xffffffffu, sum0, o);
        sum1 += __shfl_xor_sync(0xffffffffu, sum1, o);
    }
    float inv0 = 1.f / sum0, inv1 = 1.f / sum1;

    float* P0 = g_P + b * 1048576 + r0 * 1024;
    #pragma unroll
    for (int j = 0; j < 32; ++j) {
        P0[j * 32 + lane]        = s0[j] * inv0;
        P0[1024 + j * 32 + lane] = s1[j] * inv1;
    }
}

// ---------------- z = P @ v^T, fused with z_w 1x1 + output (R1 design) -----
// grid (8 n-tiles of 128, 16 batch), 256 threads. Warp = 8 channels,
// lane = 4 n-columns (l, l+32, l+64, l+96).
__global__ void __launch_bounds__(256) k_zout(
    const float* __restrict__ zw, const float* __restrict__ zb,
    float* __restrict__ out, int t)
{
    __shared__ float smem[12288];          // 48 KB, phase-unioned
    float* P_s  = smem;                    // phase 1: 128 x 33   (16896 B)
    float* v_s  = smem + 4224;             // phase 1: 64 x 32    ( 8192 B)
    float* z_s  = smem;                    // phase 2: 64 x 128   (32768 B)
    float* zw_s = smem + 8192;             // phase 2: 64 x 64    (16384 B)

    const int b   = blockIdx.y;
    const int n0  = blockIdx.x * 128;
    const int tid = threadIdx.x;
    const int w   = tid >> 5;
    const int l   = tid & 31;

    float acc[8][4];
    #pragma unroll
    for (int ci = 0; ci < 8; ++ci)
        #pragma unroll
        for (int i = 0; i < 4; ++i) acc[ci][i] = 0.f;

    for (int m0 = 0; m0 < 1024; m0 += 32) {
        for (int i = tid; i < 4096; i += 256) {
            int nl = i >> 5; int kk = i & 31;
            P_s[nl * 33 + kk] = g_P[b * 1048576 + (n0 + nl) * 1024 + m0 + kk];
        }
        for (int i = tid; i < 2048; i += 256) {
            int c = i >> 5; int kk = i & 31;
            v_s[i] = g_v[(b * 64 + c) * 1024 + m0 + kk];
        }
        __syncthreads();
        #pragma unroll 4
        for (int kk = 0; kk < 32; ++kk) {
            float pv[4];
            #pragma unroll
            for (int i = 0; i < 4; ++i) pv[i] = P_s[(l + 32 * i) * 33 + kk];
            #pragma unroll
            for (int ci = 0; ci < 8; ++ci) {
                float vv = v_s[(w * 8 + ci) * 32 + kk];
                #pragma unroll
                for (int i = 0; i < 4; ++i) acc[ci][i] += vv * pv[i];
            }
        }
        __syncthreads();
    }

    // stash z tile, stage z_w
    #pragma unroll
    for (int ci = 0; ci < 8; ++ci)
        #pragma unroll
        for (int i = 0; i < 4; ++i)
            z_s[(w * 8 + ci) * 128 + l + 32 * i] = acc[ci][i];
    for (int i = tid; i < 4096; i += 256) zw_s[i] = zw[i];
    __syncthreads();

    // attended = z_w @ z + z_b
    float acc2[8][4];
    #pragma unroll
    for (int ci = 0; ci < 8; ++ci) {
        float bv = zb[w * 8 + ci];
        #pragma unroll
        for (int i = 0; i < 4; ++i) acc2[ci][i] = bv;
    }
    #pragma unroll 8
    for (int c = 0; c < 64; ++c) {
        float pv[4];
        #pragma unroll
        for (int i = 0; i < 4; ++i) pv[i] = z_s[c * 128 + l + 32 * i];
        #pragma unroll
        for (int ci = 0; ci < 8; ++ci) {
            float wv = zw_s[(w * 8 + ci) * 64 + c];
            #pragma unroll
            for (int i = 0; i < 4; ++i) acc2[ci][i] += wv * pv[i];
        }
    }

    #pragma unroll
    for (int ci = 0; ci < 8; ++ci) {
        int oc = w * 8 + ci;
        #pragma unroll
        for (int i = 0; i < 4; ++i) {
            int n = n0 + l + 32 * i;
            float val = acc2[ci][i];
            g_h[(b * 64 + oc) * 1024 + n] = val;
            out[((b * 64 + oc) * 16 + t) * 1024 + n] = val;
        }
    }
}

// ---------------- orchestration --------------------------------------------
extern "C" void kernel_launch(void* const* d_in, const int* in_sizes, int n_in,
                              void* d_out, int out_size)
{
    (void)in_sizes; (void)n_in; (void)out_size;
    const float* X   = (const float*)d_in[0];
    const float* Wc  = (const float*)d_in[1];
    const float* bcc = (const float*)d_in[2];
    const float* Wci = (const float*)d_in[3];
    const float* Wcf = (const float*)d_in[4];
    const float* Wco = (const float*)d_in[5];
    const float* qw  = (const float*)d_in[6];
    const float* qb  = (const float*)d_in[7];
    const float* kw  = (const float*)d_in[8];
    const float* kb  = (const float*)d_in[9];
    const float* vw  = (const float*)d_in[10];
    const float* vb  = (const float*)d_in[11];
    const float* zw  = (const float*)d_in[12];
    const float* zb  = (const float*)d_in[13];
    float* out = (float*)d_out;

    k_init <<<4096, 256>>>();
    k_prepw<<<1152, 256>>>(Wc);
    for (int t = 0; t < NT; ++t) {
        k_conv_mma<<<dim3(8, 16, 4),  256>>>(X, t);
        k_gate    <<<4096,            256>>>(bcc, Wci, Wcf, Wco);
        k_qkv     <<<dim3(4, 12, 16), 256>>>(qw, qb, kw, kb, vw, vb);
        k_scores  <<<dim3(64, 16),    256>>>();
        k_zout    <<<dim3(8, 16),     256>>>(zw, zb, out, t);
    }
}

// round 9
// speedup vs baseline: 1.2940x; 1.2940x over previous
#include <cuda_runtime.h>
#include <cuda_bf16.h>
#include <math.h>
#include <cstdint>

#define BB 16
#define NT 16

// ---------------- persistent scratch (device globals; no allocation) -------
__device__ float g_h [16*64*1024];     // attended h (recurrent carry)
__device__ float g_hg[16*64*1024];     // pre-attention h (gate output)
__device__ float g_c [16*64*1024];     // cell state
__device__ float g_q [16*16*1024];
__device__ float g_k [16*16*1024];
__device__ float g_v [16*64*1024];
__device__ float g_conv[16*256*1024];  // conv output (B,256,32,32), pre-bias
// bf16 hi/lo split conv weights in mma-fragment-linear order
__device__ uint32_t g_Wfrag[294912];

// ---------------- init: zero h and c ---------------------------------------
__global__ void k_init()
{
    int i = blockIdx.x * 256 + threadIdx.x;
    g_h[i] = 0.f;
    g_c[i] = 0.f;
}

__device__ __forceinline__ float sigf(float x) { return 1.f / (1.f + __expf(-x)); }
__device__ __forceinline__ float tanh_fast(float x)
{
    return __fdividef(2.f, 1.f + __expf(-2.f * x)) - 1.f;
}
__device__ __forceinline__ uint32_t pack_bf16(float a, float b)
{
    __nv_bfloat162 h2 = __floats2bfloat162_rn(a, b);
    return *reinterpret_cast<uint32_t*>(&h2);
}
__device__ __forceinline__ float bf16_lo(float a)
{
    return a - __bfloat162float(__float2bfloat16(a));
}
__device__ __forceinline__ void mma_bf16(float* c, uint4 a, uint2 b)
{
    asm volatile(
        "mma.sync.aligned.m16n8k16.row.col.f32.bf16.bf16.f32 "
        "{%0,%1,%2,%3}, {%4,%5,%6,%7}, {%8,%9}, {%0,%1,%2,%3};"
        : "+f"(c[0]), "+f"(c[1]), "+f"(c[2]), "+f"(c[3])
        : "r"(a.x), "r"(a.y), "r"(a.z), "r"(a.w), "r"(b.x), "r"(b.y));
}

// ---------------- weight prep: split + fragment-linear layout --------------
__global__ void k_prepw(const float* __restrict__ Wc)
{
    int idx   = blockIdx.x * 256 + threadIdx.x;   // 294912
    int inner = idx & 4095;
    int outer = idx >> 12;
    int c0    = outer % 18;
    int gate  = outer / 18;
    int s     = inner & 1;
    int lane  = (inner >> 1) & 31;
    int ki    = (inner >> 6) & 3;
    int ni    = (inner >> 8) & 7;
    int sp    = (inner >> 11) & 1;

    int g = lane >> 2, tt = lane & 3;
    int n_global = gate * 64 + ni * 8 + g;
    int k0 = c0 * 64 + ki * 16 + 2 * tt + 8 * s;

    float w0, w1;
    {
        int ci = k0 / 9, r = k0 - ci * 9;
        w0 = Wc[(n_global * 128 + ci) * 9 + r];
        int k1 = k0 + 1;
        ci = k1 / 9; r = k1 - ci * 9;
        w1 = Wc[(n_global * 128 + ci) * 9 + r];
    }
    if (sp == 1) { w0 = bf16_lo(w0); w1 = bf16_lo(w1); }
    g_Wfrag[idx] = pack_bf16(w0, w1);
}

// ---------------- conv via mma.sync bf16 (R7, unchanged) -------------------
__global__ void __launch_bounds__(256, 2) k_conv_mma(
    const float* __restrict__ X, int t)
{
    __shared__ uint32_t sm_u[8448];
    uint32_t* A_s  = sm_u;
    uint32_t* Bh_s = sm_u + 4096;
    uint32_t* Bl_s = sm_u + 6144;

    const int tid  = threadIdx.x;
    const int wid  = tid >> 5;
    const int lane = tid & 31;
    const int mt   = blockIdx.x;
    const int b    = blockIdx.y;
    const int gate = blockIdx.z;
    const int n0   = gate * 64;
    const int wm   = wid >> 1;
    const int wn   = wid & 1;
    const int g    = lane >> 2, tt = lane & 3;

    const float* Xb = X + (b * 64 * 16 + t) * 1024;
    const float* Hb = g_h + b * 64 * 1024;

    float acc[2][4][4];
    #pragma unroll
    for (int im = 0; im < 2; ++im)
        #pragma unroll
        for (int in = 0; in < 4; ++in)
            #pragma unroll
            for (int q = 0; q < 4; ++q) acc[im][in][q] = 0.f;

    float av[32];
    const uint4* A4  = reinterpret_cast<const uint4*>(A_s);
    const uint2* Bh2 = reinterpret_cast<const uint2*>(Bh_s);
    const uint2* Bl2 = reinterpret_cast<const uint2*>(Bl_s);

    for (int c0 = 0; c0 < 18; ++c0) {
        #pragma unroll
        for (int j = 0; j < 16; ++j) {
            int slot = j * 256 + tid;
            int s  = slot & 3;
            int ln = (slot >> 2) & 31;
            int ki = (slot >> 7) & 3;
            int mi = slot >> 9;
            int gg = ln >> 2, t4 = ln & 3;
            int m  = mi * 16 + gg + 8 * (s & 1);
            int kb = c0 * 64 + ki * 16 + 2 * t4 + 8 * (s >> 1);
            int pix = mt * 128 + m;
            int py = pix >> 5, px = pix & 31;
            float a0 = 0.f, a1 = 0.f;
            #pragma unroll
            for (int h = 0; h < 2; ++h) {
                int kg = kb + h;
                int ci = kg / 9, r = kg - ci * 9;
                int dy = r / 3 - 1, dx = r - (r / 3) * 3 - 1;
                int ys = py + dy, xs = px + dx;
                float a = 0.f;
                if ((unsigned)ys < 32u && (unsigned)xs < 32u) {
                    int sp2 = ys * 32 + xs;
                    a = (ci < 64) ? Xb[ci * 16384 + sp2]
                                  : Hb[(ci - 64) * 1024 + sp2];
                }
                if (h == 0) a0 = a; else a1 = a;
            }
            av[2 * j] = a0; av[2 * j + 1] = a1;
            A_s[slot] = pack_bf16(a0, a1);
        }
        {
            const uint4* src = reinterpret_cast<const uint4*>(
                g_Wfrag + (gate * 18 + c0) * 4096);
            uint4* dh = reinterpret_cast<uint4*>(Bh_s);
            uint4* dl = reinterpret_cast<uint4*>(Bl_s);
            dh[tid]       = src[tid];
            dh[tid + 256] = src[tid + 256];
            dl[tid]       = src[tid + 512];
            dl[tid + 256] = src[tid + 768];
        }
        __syncthreads();

        #pragma unroll
        for (int ki = 0; ki < 4; ++ki) {
            uint4 af0 = A4[((wm * 2    ) * 4 + ki) * 32 + lane];
            uint4 af1 = A4[((wm * 2 + 1) * 4 + ki) * 32 + lane];
            #pragma unroll
            for (int in = 0; in < 4; ++in) {
                int ni = wn * 4 + in;
                uint2 bh = Bh2[(ni * 4 + ki) * 32 + lane];
                uint2 bl = Bl2[(ni * 4 + ki) * 32 + lane];
                mma_bf16(acc[0][in], af0, bh);
                mma_bf16(acc[1][in], af1, bh);
                mma_bf16(acc[0][in], af0, bl);
                mma_bf16(acc[1][in], af1, bl);
            }
        }
        __syncthreads();

        #pragma unroll
        for (int j = 0; j < 16; ++j) {
            int slot = j * 256 + tid;
            A_s[slot] = pack_bf16(bf16_lo(av[2 * j]), bf16_lo(av[2 * j + 1]));
        }
        __syncthreads();

        #pragma unroll
        for (int ki = 0; ki < 4; ++ki) {
            uint4 af0 = A4[((wm * 2    ) * 4 + ki) * 32 + lane];
            uint4 af1 = A4[((wm * 2 + 1) * 4 + ki) * 32 + lane];
            #pragma unroll
            for (int in = 0; in < 4; ++in) {
                int ni = wn * 4 + in;
                uint2 bh = Bh2[(ni * 4 + ki) * 32 + lane];
                mma_bf16(acc[0][in], af0, bh);
                mma_bf16(acc[1][in], af1, bh);
            }
        }
        __syncthreads();
    }

    float* out_s = reinterpret_cast<float*>(sm_u);
    #pragma unroll
    for (int im = 0; im < 2; ++im) {
        int mi = wm * 2 + im;
        int m  = mi * 16 + g;
        #pragma unroll
        for (int in = 0; in < 4; ++in) {
            int ni = wn * 4 + in;
            int n  = ni * 8 + 2 * tt;
            out_s[ n      * 132 + m    ] = acc[im][in][0];
            out_s[(n + 1) * 132 + m    ] = acc[im][in][1];
            out_s[ n      * 132 + m + 8] = acc[im][in][2];
            out_s[(n + 1) * 132 + m + 8] = acc[im][in][3];
        }
    }
    __syncthreads();
    #pragma unroll
    for (int j = 0; j < 32; ++j) {
        int idx = j * 256 + tid;
        int n = idx >> 7, m = idx & 127;
        g_conv[(b * 256 + n0 + n) * 1024 + mt * 128 + m] = out_s[n * 132 + m];
    }
}

// ---------------- ConvLSTM gating (elementwise) ----------------------------
__global__ void k_gate(const float* __restrict__ bc,
                       const float* __restrict__ Wci,
                       const float* __restrict__ Wcf,
                       const float* __restrict__ Wco)
{
    int idx = blockIdx.x * 256 + threadIdx.x;
    int b   = idx >> 16;
    int c   = (idx >> 10) & 63;
    int pos = idx & 1023;
    int cb  = (b * 256 + c) * 1024 + pos;

    float ic = g_conv[cb]              + bc[c];
    float fc = g_conv[cb + 64 * 1024]  + bc[64 + c];
    float gc = g_conv[cb + 128 * 1024] + bc[128 + c];
    float oc = g_conv[cb + 192 * 1024] + bc[192 + c];
    float cp = g_c[idx];
    int   wp = c * 1024 + pos;

    float i  = sigf(ic + Wci[wp] * cp);
    float f  = sigf(fc + Wcf[wp] * cp);
    float nc = f * cp + i * tanh_fast(gc);
    float o  = sigf(oc + Wco[wp] * nc);
    g_c[idx]  = nc;
    g_hg[idx] = o * tanh_fast(nc);
}

// ---------------- q,k,v 1x1 convs ------------------------------------------
__global__ void k_qkv(const float* __restrict__ qw, const float* __restrict__ qb,
                      const float* __restrict__ kw, const float* __restrict__ kb,
                      const float* __restrict__ vw, const float* __restrict__ vb)
{
    __shared__ float h_s[32 * 256];
    __shared__ float w_s[8 * 64];

    const int p0  = blockIdx.x * 256;
    const int oc0 = blockIdx.y * 8;
    const int b   = blockIdx.z;
    const int tid = threadIdx.x;

    for (int i = tid; i < 512; i += 256) {
        int j = i >> 6; int c = i & 63; int oc = oc0 + j;
        w_s[i] = (oc < 16) ? qw[oc * 64 + c]
               : (oc < 32) ? kw[(oc - 16) * 64 + c]
                           : vw[(oc - 32) * 64 + c];
    }

    float acc[8];
    #pragma unroll
    for (int j = 0; j < 8; ++j) {
        int oc = oc0 + j;
        acc[j] = (oc < 16) ? qb[oc] : (oc < 32) ? kb[oc - 16] : vb[oc - 32];
    }

    for (int chh = 0; chh < 2; ++chh) {
        __syncthreads();
        for (int i = tid; i < 8192; i += 256) {
            int c = i >> 8; int j = i & 255;
            h_s[i] = g_hg[(b * 64 + chh * 32 + c) * 1024 + p0 + j];
        }
        __syncthreads();
        #pragma unroll 8
        for (int c = 0; c < 32; ++c) {
            float hv = h_s[c * 256 + tid];
            #pragma unroll
            for (int j = 0; j < 8; ++j)
                acc[j] += w_s[j * 64 + chh * 32 + c] * hv;
        }
    }

    int pos = p0 + tid;
    #pragma unroll
    for (int j = 0; j < 8; ++j) {
        int oc = oc0 + j;
        if (oc < 16)      g_q[(b * 16 + oc) * 1024 + pos]        = acc[j];
        else if (oc < 32) g_k[(b * 16 + (oc - 16)) * 1024 + pos] = acc[j];
        else              g_v[(b * 64 + (oc - 32)) * 1024 + pos] = acc[j];
    }
}

// ---------------- flash attention via mma (scores+softmax+P@v+z_w) ---------
// grid (8 n-tiles of 128 rows, 16 batch), 256 threads = 8 warps.
// Warp owns 16 rows. Online softmax over m in 16 chunks of 64.
__global__ void __launch_bounds__(256) k_flash(
    const float* __restrict__ zw, const float* __restrict__ zb,
    float* __restrict__ out, int t)
{
    __shared__ uint32_t pool[12288];               // 48 KB
    float*    q_s  = reinterpret_cast<float*>(pool);      // [128][17] = 2176
    uint32_t* khi2 = pool + 2176;                  // [64 m][8 cpair]
    uint32_t* klo2 = pool + 2688;
    uint32_t* vhi2 = pool + 3200;                  // [64 c][32 mpair]
    uint32_t* vlo2 = pool + 5248;                  // ends 7296
    float*    z_s  = reinterpret_cast<float*>(pool);          // epi: [64][128]
    float*    zw_s = reinterpret_cast<float*>(pool + 8192);   // epi: 4096

    const int b    = blockIdx.y;
    const int n0   = blockIdx.x * 128;
    const int tid  = threadIdx.x;
    const int w    = tid >> 5;
    const int lane = tid & 31;
    const int g    = lane >> 2, tt = lane & 3;
    const int rA   = w * 16 + g;                   // local rows rA, rA+8

    // ---- stage q tile [128 rows][16 ch] ----
    for (int i = tid; i < 2048; i += 256) {
        int c = i >> 7, r = i & 127;
        q_s[r * 17 + c] = g_q[(b * 16 + c) * 1024 + n0 + r];
    }
    __syncthreads();

    // ---- build q A-fragments (hi/lo) ----
    uint4 qh, ql;
    {
        float x0 = q_s[rA * 17 + 2 * tt],           x1 = q_s[rA * 17 + 2 * tt + 1];
        float x2 = q_s[(rA + 8) * 17 + 2 * tt],     x3 = q_s[(rA + 8) * 17 + 2 * tt + 1];
        float x4 = q_s[rA * 17 + 8 + 2 * tt],       x5 = q_s[rA * 17 + 9 + 2 * tt];
        float x6 = q_s[(rA + 8) * 17 + 8 + 2 * tt], x7 = q_s[(rA + 8) * 17 + 9 + 2 * tt];
        qh = make_uint4(pack_bf16(x0, x1), pack_bf16(x2, x3),
                        pack_bf16(x4, x5), pack_bf16(x6, x7));
        ql = make_uint4(pack_bf16(bf16_lo(x0), bf16_lo(x1)),
                        pack_bf16(bf16_lo(x2), bf16_lo(x3)),
                        pack_bf16(bf16_lo(x4), bf16_lo(x5)),
                        pack_bf16(bf16_lo(x6), bf16_lo(x7)));
    }

    float z[8][4];
    #pragma unroll
    for (int cj = 0; cj < 8; ++cj)
        #pragma unroll
        for (int q = 0; q < 4; ++q) z[cj][q] = 0.f;
    float Ma = -1e30f, Mb = -1e30f, la = 0.f, lb = 0.f;

    for (int mch = 0; mch < 16; ++mch) {
        const int mb = mch * 64;
        __syncthreads();
        // stage k chunk: [64 m][16 ch] -> bf16x2 ch-pairs
        for (int i = tid; i < 512; i += 256) {
            int m = i & 63, c2 = i >> 6;
            float k0 = g_k[(b * 16 + 2 * c2) * 1024 + mb + m];
            float k1 = g_k[(b * 16 + 2 * c2 + 1) * 1024 + mb + m];
            khi2[m * 8 + c2] = pack_bf16(k0, k1);
            klo2[m * 8 + c2] = pack_bf16(bf16_lo(k0), bf16_lo(k1));
        }
        // stage v chunk: [64 c][64 m] -> bf16x2 m-pairs
        for (int i = tid; i < 2048; i += 256) {
            int c = i >> 5, mp = i & 31;
            float2 vv = *reinterpret_cast<const float2*>(
                &g_v[(b * 64 + c) * 1024 + mb + 2 * mp]);
            vhi2[c * 32 + mp] = pack_bf16(vv.x, vv.y);
            vlo2[c * 32 + mp] = pack_bf16(bf16_lo(vv.x), bf16_lo(vv.y));
        }
        __syncthreads();

        // ---- S = q . k^T (128 x 64), 3-pass hi/lo ----
        float S[8][4];
        #pragma unroll
        for (int j = 0; j < 8; ++j)
            #pragma unroll
            for (int q = 0; q < 4; ++q) S[j][q] = 0.f;
        #pragma unroll
        for (int j = 0; j < 8; ++j) {
            int m = j * 8 + g;
            uint2 bh = make_uint2(khi2[m * 8 + tt], khi2[m * 8 + tt + 4]);
            uint2 bl = make_uint2(klo2[m * 8 + tt], klo2[m * 8 + tt + 4]);
            mma_bf16(S[j], qh, bh);
            mma_bf16(S[j], qh, bl);
            mma_bf16(S[j], ql, bh);
        }

        // ---- online softmax ----
        float cma = -1e30f, cmb = -1e30f;
        #pragma unroll
        for (int j = 0; j < 8; ++j) {
            cma = fmaxf(cma, fmaxf(S[j][0], S[j][1]));
            cmb = fmaxf(cmb, fmaxf(S[j][2], S[j][3]));
        }
        cma = fmaxf(cma, __shfl_xor_sync(0xffffffffu, cma, 1));
        cma = fmaxf(cma, __shfl_xor_sync(0xffffffffu, cma, 2));
        cmb = fmaxf(cmb, __shfl_xor_sync(0xffffffffu, cmb, 1));
        cmb = fmaxf(cmb, __shfl_xor_sync(0xffffffffu, cmb, 2));
        float Mna = fmaxf(Ma, cma), Mnb = fmaxf(Mb, cmb);
        float alA = __expf(Ma - Mna), alB = __expf(Mb - Mnb);
        Ma = Mna; Mb = Mnb;

        float sa = 0.f, sb = 0.f;
        #pragma unroll
        for (int j = 0; j < 8; ++j) {
            S[j][0] = __expf(S[j][0] - Ma); sa += S[j][0];
            S[j][1] = __expf(S[j][1] - Ma); sa += S[j][1];
            S[j][2] = __expf(S[j][2] - Mb); sb += S[j][2];
            S[j][3] = __expf(S[j][3] - Mb); sb += S[j][3];
        }
        sa += __shfl_xor_sync(0xffffffffu, sa, 1);
        sa += __shfl_xor_sync(0xffffffffu, sa, 2);
        sb += __shfl_xor_sync(0xffffffffu, sb, 1);
        sb += __shfl_xor_sync(0xffffffffu, sb, 2);
        la = la * alA + sa;
        lb = lb * alB + sb;
        #pragma unroll
        for (int cj = 0; cj < 8; ++cj) {
            z[cj][0] *= alA; z[cj][1] *= alA;
            z[cj][2] *= alB; z[cj][3] *= alB;
        }

        // ---- z += P @ v^T, 3-pass hi/lo; P frags direct from S regs ----
        #pragma unroll
        for (int ks = 0; ks < 4; ++ks) {
            uint4 ah = make_uint4(
                pack_bf16(S[2 * ks][0], S[2 * ks][1]),
                pack_bf16(S[2 * ks][2], S[2 * ks][3]),
                pack_bf16(S[2 * ks + 1][0], S[2 * ks + 1][1]),
                pack_bf16(S[2 * ks + 1][2], S[2 * ks + 1][3]));
            uint4 al = make_uint4(
                pack_bf16(bf16_lo(S[2 * ks][0]), bf16_lo(S[2 * ks][1])),
                pack_bf16(bf16_lo(S[2 * ks][2]), bf16_lo(S[2 * ks][3])),
                pack_bf16(bf16_lo(S[2 * ks + 1][0]), bf16_lo(S[2 * ks + 1][1])),
                pack_bf16(bf16_lo(S[2 * ks + 1][2]), bf16_lo(S[2 * ks + 1][3])));
            #pragma unroll
            for (int cj = 0; cj < 8; ++cj) {
                int c = cj * 8 + g;
                uint2 bh = make_uint2(vhi2[c * 32 + ks * 8 + tt],
                                      vhi2[c * 32 + ks * 8 + tt + 4]);
                uint2 bl = make_uint2(vlo2[c * 32 + ks * 8 + tt],
                                      vlo2[c * 32 + ks * 8 + tt + 4]);
                mma_bf16(z[cj], ah, bh);
                mma_bf16(z[cj], ah, bl);
                mma_bf16(z[cj], al, bh);
            }
        }
    }

    // ---- epilogue: normalize, z -> smem [c][128], then z_w 1x1 ----
    float lia = 1.f / la, lib = 1.f / lb;
    __syncthreads();
    #pragma unroll
    for (int cj = 0; cj < 8; ++cj) {
        int c = cj * 8 + 2 * tt;
        z_s[ c      * 128 + w * 16 + g    ] = z[cj][0] * lia;
        z_s[(c + 1) * 128 + w * 16 + g    ] = z[cj][1] * lia;
        z_s[ c      * 128 + w * 16 + g + 8] = z[cj][2] * lib;
        z_s[(c + 1) * 128 + w * 16 + g + 8] = z[cj][3] * lib;
    }
    for (int i = tid; i < 4096; i += 256) zw_s[i] = zw[i];
    __syncthreads();

    const int l = lane;
    float acc2[8][4];
    #pragma unroll
    for (int ci = 0; ci < 8; ++ci) {
        float bv = zb[w * 8 + ci];
        #pragma unroll
        for (int i = 0; i < 4; ++i) acc2[ci][i] = bv;
    }
    #pragma unroll 8
    for (int c = 0; c < 64; ++c) {
        float pv[4];
        #pragma unroll
        for (int i = 0; i < 4; ++i) pv[i] = z_s[c * 128 + l + 32 * i];
        #pragma unroll
        for (int ci = 0; ci < 8; ++ci) {
            float wv = zw_s[(w * 8 + ci) * 64 + c];
            #pragma unroll
            for (int i = 0; i < 4; ++i) acc2[ci][i] += wv * pv[i];
        }
    }
    #pragma unroll
    for (int ci = 0; ci < 8; ++ci) {
        int oc = w * 8 + ci;
        #pragma unroll
        for (int i = 0; i < 4; ++i) {
            int n = n0 + l + 32 * i;
            float val = acc2[ci][i];
            g_h[(b * 64 + oc) * 1024 + n] = val;
            out[((b * 64 + oc) * 16 + t) * 1024 + n] = val;
        }
    }
}

// ---------------- orchestration --------------------------------------------
extern "C" void kernel_launch(void* const* d_in, const int* in_sizes, int n_in,
                              void* d_out, int out_size)
{
    (void)in_sizes; (void)n_in; (void)out_size;
    const float* X   = (const float*)d_in[0];
    const float* Wc  = (const float*)d_in[1];
    const float* bcc = (const float*)d_in[2];
    const float* Wci = (const float*)d_in[3];
    const float* Wcf = (const float*)d_in[4];
    const float* Wco = (const float*)d_in[5];
    const float* qw  = (const float*)d_in[6];
    const float* qb  = (const float*)d_in[7];
    const float* kw  = (const float*)d_in[8];
    const float* kb  = (const float*)d_in[9];
    const float* vw  = (const float*)d_in[10];
    const float* vb  = (const float*)d_in[11];
    const float* zw  = (const float*)d_in[12];
    const float* zb  = (const float*)d_in[13];
    float* out = (float*)d_out;

    k_init <<<4096, 256>>>();
    k_prepw<<<1152, 256>>>(Wc);
    for (int t = 0; t < NT; ++t) {
        k_conv_mma<<<dim3(8, 16, 4),  256>>>(X, t);
        k_gate    <<<4096,            256>>>(bcc, Wci, Wcf, Wco);
        k_qkv     <<<dim3(4, 12, 16), 256>>>(qw, qb, kw, kb, vw, vb);
        k_flash   <<<dim3(8, 16),     256>>>(zw, zb, out, t);
    }
}

// round 10
// speedup vs baseline: 1.4171x; 1.0951x over previous
#include <cuda_runtime.h>
#include <cuda_bf16.h>
#include <math.h>
#include <cstdint>

#define BB 16
#define NT 16

// ---------------- persistent scratch (device globals; no allocation) -------
__device__ float g_h [16*64*1024];     // attended h (recurrent carry)
__device__ float g_hg[16*64*1024];     // pre-attention h (gate output)
__device__ float g_c [16*64*1024];     // cell state
__device__ float g_q [16*16*1024];
__device__ float g_k [16*16*1024];
__device__ float g_v [16*64*1024];
__device__ float g_conv[16*256*1024];  // conv output (B,256,32,32), pre-bias
// bf16 hi/lo split conv weights in mma-fragment-linear order
__device__ uint32_t g_Wfrag[294912];

// ---------------- init: zero h and c ---------------------------------------
__global__ void k_init()
{
    int i = blockIdx.x * 256 + threadIdx.x;
    g_h[i] = 0.f;
    g_c[i] = 0.f;
}

__device__ __forceinline__ float sigf(float x) { return 1.f / (1.f + __expf(-x)); }
__device__ __forceinline__ float tanh_fast(float x)
{
    return __fdividef(2.f, 1.f + __expf(-2.f * x)) - 1.f;
}
__device__ __forceinline__ uint32_t pack_bf16(float a, float b)
{
    __nv_bfloat162 h2 = __floats2bfloat162_rn(a, b);
    return *reinterpret_cast<uint32_t*>(&h2);
}
__device__ __forceinline__ float bf16_lo(float a)
{
    return a - __bfloat162float(__float2bfloat16(a));
}
__device__ __forceinline__ void mma_bf16(float* c, uint4 a, uint2 b)
{
    asm volatile(
        "mma.sync.aligned.m16n8k16.row.col.f32.bf16.bf16.f32 "
        "{%0,%1,%2,%3}, {%4,%5,%6,%7}, {%8,%9}, {%0,%1,%2,%3};"
        : "+f"(c[0]), "+f"(c[1]), "+f"(c[2]), "+f"(c[3])
        : "r"(a.x), "r"(a.y), "r"(a.z), "r"(a.w), "r"(b.x), "r"(b.y));
}

// ---------------- weight prep: split + fragment-linear layout --------------
__global__ void k_prepw(const float* __restrict__ Wc)
{
    int idx   = blockIdx.x * 256 + threadIdx.x;   // 294912
    int inner = idx & 4095;
    int outer = idx >> 12;
    int c0    = outer % 18;
    int gate  = outer / 18;
    int s     = inner & 1;
    int lane  = (inner >> 1) & 31;
    int ki    = (inner >> 6) & 3;
    int ni    = (inner >> 8) & 7;
    int sp    = (inner >> 11) & 1;

    int g = lane >> 2, tt = lane & 3;
    int n_global = gate * 64 + ni * 8 + g;
    int k0 = c0 * 64 + ki * 16 + 2 * tt + 8 * s;

    float w0, w1;
    {
        int ci = k0 / 9, r = k0 - ci * 9;
        w0 = Wc[(n_global * 128 + ci) * 9 + r];
        int k1 = k0 + 1;
        ci = k1 / 9; r = k1 - ci * 9;
        w1 = Wc[(n_global * 128 + ci) * 9 + r];
    }
    if (sp == 1) { w0 = bf16_lo(w0); w1 = bf16_lo(w1); }
    g_Wfrag[idx] = pack_bf16(w0, w1);
}

// ---------------- conv via mma.sync bf16 -----------------------------------
// Merged A hi/lo staging: one stage round + one mma round per chunk (2 syncs).
__global__ void __launch_bounds__(256, 2) k_conv_mma(
    const float* __restrict__ X, int t)
{
    __shared__ uint32_t sm_u[12288];       // 48 KB: Ah|Al|Bh|Bl
    uint32_t* Ah_s = sm_u;                 // 4096
    uint32_t* Al_s = sm_u + 4096;          // 4096
    uint32_t* Bh_s = sm_u + 8192;          // 2048
    uint32_t* Bl_s = sm_u + 10240;         // 2048

    const int tid  = threadIdx.x;
    const int wid  = tid >> 5;
    const int lane = tid & 31;
    const int mt   = blockIdx.x;
    const int b    = blockIdx.y;
    const int gate = blockIdx.z;
    const int n0   = gate * 64;
    const int wm   = wid >> 1;
    const int wn   = wid & 1;
    const int g    = lane >> 2, tt = lane & 3;

    const float* Xb = X + (b * 64 * 16 + t) * 1024;
    const float* Hb = g_h + b * 64 * 1024;

    float acc[2][4][4];
    #pragma unroll
    for (int im = 0; im < 2; ++im)
        #pragma unroll
        for (int in = 0; in < 4; ++in)
            #pragma unroll
            for (int q = 0; q < 4; ++q) acc[im][in][q] = 0.f;

    const uint4* Ah4 = reinterpret_cast<const uint4*>(Ah_s);
    const uint4* Al4 = reinterpret_cast<const uint4*>(Al_s);
    const uint2* Bh2 = reinterpret_cast<const uint2*>(Bh_s);
    const uint2* Bl2 = reinterpret_cast<const uint2*>(Bl_s);

    for (int c0 = 0; c0 < 18; ++c0) {
        // ---- stage A hi + lo (im2col gather, fragment-linear) ----
        #pragma unroll
        for (int j = 0; j < 16; ++j) {
            int slot = j * 256 + tid;
            int s  = slot & 3;
            int ln = (slot >> 2) & 31;
            int ki = (slot >> 7) & 3;
            int mi = slot >> 9;
            int gg = ln >> 2, t4 = ln & 3;
            int m  = mi * 16 + gg + 8 * (s & 1);
            int kb = c0 * 64 + ki * 16 + 2 * t4 + 8 * (s >> 1);
            int pix = mt * 128 + m;
            int py = pix >> 5, px = pix & 31;
            float a0 = 0.f, a1 = 0.f;
            #pragma unroll
            for (int h = 0; h < 2; ++h) {
                int kg = kb + h;
                int ci = kg / 9, r = kg - ci * 9;
                int dy = r / 3 - 1, dx = r - (r / 3) * 3 - 1;
                int ys = py + dy, xs = px + dx;
                float a = 0.f;
                if ((unsigned)ys < 32u && (unsigned)xs < 32u) {
                    int sp2 = ys * 32 + xs;
                    a = (ci < 64) ? Xb[ci * 16384 + sp2]
                                  : Hb[(ci - 64) * 1024 + sp2];
                }
                if (h == 0) a0 = a; else a1 = a;
            }
            Ah_s[slot] = pack_bf16(a0, a1);
            Al_s[slot] = pack_bf16(bf16_lo(a0), bf16_lo(a1));
        }
        // ---- stage Bh, Bl ----
        {
            const uint4* src = reinterpret_cast<const uint4*>(
                g_Wfrag + (gate * 18 + c0) * 4096);
            uint4* dh = reinterpret_cast<uint4*>(Bh_s);
            uint4* dl = reinterpret_cast<uint4*>(Bl_s);
            dh[tid]       = src[tid];
            dh[tid + 256] = src[tid + 256];
            dl[tid]       = src[tid + 512];
            dl[tid + 256] = src[tid + 768];
        }
        __syncthreads();

        // ---- all 3 hi/lo passes back-to-back ----
        #pragma unroll
        for (int ki = 0; ki < 4; ++ki) {
            uint4 a0h = Ah4[((wm * 2    ) * 4 + ki) * 32 + lane];
            uint4 a1h = Ah4[((wm * 2 + 1) * 4 + ki) * 32 + lane];
            uint4 a0l = Al4[((wm * 2    ) * 4 + ki) * 32 + lane];
            uint4 a1l = Al4[((wm * 2 + 1) * 4 + ki) * 32 + lane];
            #pragma unroll
            for (int in = 0; in < 4; ++in) {
                int ni = wn * 4 + in;
                uint2 bh = Bh2[(ni * 4 + ki) * 32 + lane];
                uint2 bl = Bl2[(ni * 4 + ki) * 32 + lane];
                mma_bf16(acc[0][in], a0h, bh);
                mma_bf16(acc[1][in], a1h, bh);
                mma_bf16(acc[0][in], a0h, bl);
                mma_bf16(acc[1][in], a1h, bl);
                mma_bf16(acc[0][in], a0l, bh);
                mma_bf16(acc[1][in], a1l, bh);
            }
        }
        __syncthreads();
    }

    float* out_s = reinterpret_cast<float*>(sm_u);
    #pragma unroll
    for (int im = 0; im < 2; ++im) {
        int mi = wm * 2 + im;
        int m  = mi * 16 + g;
        #pragma unroll
        for (int in = 0; in < 4; ++in) {
            int ni = wn * 4 + in;
            int n  = ni * 8 + 2 * tt;
            out_s[ n      * 132 + m    ] = acc[im][in][0];
            out_s[(n + 1) * 132 + m    ] = acc[im][in][1];
            out_s[ n      * 132 + m + 8] = acc[im][in][2];
            out_s[(n + 1) * 132 + m + 8] = acc[im][in][3];
        }
    }
    __syncthreads();
    #pragma unroll
    for (int j = 0; j < 32; ++j) {
        int idx = j * 256 + tid;
        int n = idx >> 7, m = idx & 127;
        g_conv[(b * 256 + n0 + n) * 1024 + mt * 128 + m] = out_s[n * 132 + m];
    }
}

// ---------------- ConvLSTM gating (elementwise) ----------------------------
__global__ void k_gate(const float* __restrict__ bc,
                       const float* __restrict__ Wci,
                       const float* __restrict__ Wcf,
                       const float* __restrict__ Wco)
{
    int idx = blockIdx.x * 256 + threadIdx.x;
    int b   = idx >> 16;
    int c   = (idx >> 10) & 63;
    int pos = idx & 1023;
    int cb  = (b * 256 + c) * 1024 + pos;

    float ic = g_conv[cb]              + bc[c];
    float fc = g_conv[cb + 64 * 1024]  + bc[64 + c];
    float gc = g_conv[cb + 128 * 1024] + bc[128 + c];
    float oc = g_conv[cb + 192 * 1024] + bc[192 + c];
    float cp = g_c[idx];
    int   wp = c * 1024 + pos;

    float i  = sigf(ic + Wci[wp] * cp);
    float f  = sigf(fc + Wcf[wp] * cp);
    float nc = f * cp + i * tanh_fast(gc);
    float o  = sigf(oc + Wco[wp] * nc);
    g_c[idx]  = nc;
    g_hg[idx] = o * tanh_fast(nc);
}

// ---------------- q,k,v 1x1 convs ------------------------------------------
__global__ void k_qkv(const float* __restrict__ qw, const float* __restrict__ qb,
                      const float* __restrict__ kw, const float* __restrict__ kb,
                      const float* __restrict__ vw, const float* __restrict__ vb)
{
    __shared__ float h_s[32 * 256];
    __shared__ float w_s[8 * 64];

    const int p0  = blockIdx.x * 256;
    const int oc0 = blockIdx.y * 8;
    const int b   = blockIdx.z;
    const int tid = threadIdx.x;

    for (int i = tid; i < 512; i += 256) {
        int j = i >> 6; int c = i & 63; int oc = oc0 + j;
        w_s[i] = (oc < 16) ? qw[oc * 64 + c]
               : (oc < 32) ? kw[(oc - 16) * 64 + c]
                           : vw[(oc - 32) * 64 + c];
    }

    float acc[8];
    #pragma unroll
    for (int j = 0; j < 8; ++j) {
        int oc = oc0 + j;
        acc[j] = (oc < 16) ? qb[oc] : (oc < 32) ? kb[oc - 16] : vb[oc - 32];
    }

    for (int chh = 0; chh < 2; ++chh) {
        __syncthreads();
        for (int i = tid; i < 8192; i += 256) {
            int c = i >> 8; int j = i & 255;
            h_s[i] = g_hg[(b * 64 + chh * 32 + c) * 1024 + p0 + j];
        }
        __syncthreads();
        #pragma unroll 8
        for (int c = 0; c < 32; ++c) {
            float hv = h_s[c * 256 + tid];
            #pragma unroll
            for (int j = 0; j < 8; ++j)
                acc[j] += w_s[j * 64 + chh * 32 + c] * hv;
        }
    }

    int pos = p0 + tid;
    #pragma unroll
    for (int j = 0; j < 8; ++j) {
        int oc = oc0 + j;
        if (oc < 16)      g_q[(b * 16 + oc) * 1024 + pos]        = acc[j];
        else if (oc < 32) g_k[(b * 16 + (oc - 16)) * 1024 + pos] = acc[j];
        else              g_v[(b * 64 + (oc - 32)) * 1024 + pos] = acc[j];
    }
}

// ---------------- flash attention via mma ----------------------------------
// grid (8 n-tiles of 128 rows, 16 batch), 256 threads = 8 warps.
// Conflict-free smem strides: k stride 12 (bank=12g+tt perm), v stride 36
// (bank=4g+tt perm).
__global__ void __launch_bounds__(256) k_flash(
    const float* __restrict__ zw, const float* __restrict__ zb,
    float* __restrict__ out, int t)
{
    __shared__ uint32_t pool[12288];               // 48 KB
    float*    q_s  = reinterpret_cast<float*>(pool);   // [128][17] = 2176
    uint32_t* khi2 = pool + 2176;                  // [64 m][12] (8 used)
    uint32_t* klo2 = pool + 2944;
    uint32_t* vhi2 = pool + 3712;                  // [64 c][36] (32 used)
    uint32_t* vlo2 = pool + 6016;                  // ends 8320
    float*    z_s  = reinterpret_cast<float*>(pool);          // epi: [64][128]
    float*    zw_s = reinterpret_cast<float*>(pool + 8192);   // epi: 4096

    const int b    = blockIdx.y;
    const int n0   = blockIdx.x * 128;
    const int tid  = threadIdx.x;
    const int w    = tid >> 5;
    const int lane = tid & 31;
    const int g    = lane >> 2, tt = lane & 3;
    const int rA   = w * 16 + g;

    // ---- stage q tile [128 rows][16 ch] ----
    for (int i = tid; i < 2048; i += 256) {
        int c = i >> 7, r = i & 127;
        q_s[r * 17 + c] = g_q[(b * 16 + c) * 1024 + n0 + r];
    }
    __syncthreads();

    // ---- build q A-fragments (hi/lo) ----
    uint4 qh, ql;
    {
        float x0 = q_s[rA * 17 + 2 * tt],           x1 = q_s[rA * 17 + 2 * tt + 1];
        float x2 = q_s[(rA + 8) * 17 + 2 * tt],     x3 = q_s[(rA + 8) * 17 + 2 * tt + 1];
        float x4 = q_s[rA * 17 + 8 + 2 * tt],       x5 = q_s[rA * 17 + 9 + 2 * tt];
        float x6 = q_s[(rA + 8) * 17 + 8 + 2 * tt], x7 = q_s[(rA + 8) * 17 + 9 + 2 * tt];
        qh = make_uint4(pack_bf16(x0, x1), pack_bf16(x2, x3),
                        pack_bf16(x4, x5), pack_bf16(x6, x7));
        ql = make_uint4(pack_bf16(bf16_lo(x0), bf16_lo(x1)),
                        pack_bf16(bf16_lo(x2), bf16_lo(x3)),
                        pack_bf16(bf16_lo(x4), bf16_lo(x5)),
                        pack_bf16(bf16_lo(x6), bf16_lo(x7)));
    }

    float z[8][4];
    #pragma unroll
    for (int cj = 0; cj < 8; ++cj)
        #pragma unroll
        for (int q = 0; q < 4; ++q) z[cj][q] = 0.f;
    float Ma = -1e30f, Mb = -1e30f, la = 0.f, lb = 0.f;

    for (int mch = 0; mch < 16; ++mch) {
        const int mb = mch * 64;
        __syncthreads();
        // stage k chunk: [64 m][16 ch] -> bf16x2 ch-pairs, stride 12
        for (int i = tid; i < 512; i += 256) {
            int m = i & 63, c2 = i >> 6;
            float k0 = g_k[(b * 16 + 2 * c2) * 1024 + mb + m];
            float k1 = g_k[(b * 16 + 2 * c2 + 1) * 1024 + mb + m];
            khi2[m * 12 + c2] = pack_bf16(k0, k1);
            klo2[m * 12 + c2] = pack_bf16(bf16_lo(k0), bf16_lo(k1));
        }
        // stage v chunk: [64 c][64 m] -> bf16x2 m-pairs, stride 36
        for (int i = tid; i < 2048; i += 256) {
            int c = i >> 5, mp = i & 31;
            float2 vv = *reinterpret_cast<const float2*>(
                &g_v[(b * 64 + c) * 1024 + mb + 2 * mp]);
            vhi2[c * 36 + mp] = pack_bf16(vv.x, vv.y);
            vlo2[c * 36 + mp] = pack_bf16(bf16_lo(vv.x), bf16_lo(vv.y));
        }
        __syncthreads();

        // ---- S = q . k^T (128 x 64), 3-pass hi/lo ----
        float S[8][4];
        #pragma unroll
        for (int j = 0; j < 8; ++j)
            #pragma unroll
            for (int q = 0; q < 4; ++q) S[j][q] = 0.f;
        #pragma unroll
        for (int j = 0; j < 8; ++j) {
            int m = j * 8 + g;
            uint2 bh = make_uint2(khi2[m * 12 + tt], khi2[m * 12 + tt + 4]);
            uint2 bl = make_uint2(klo2[m * 12 + tt], klo2[m * 12 + tt + 4]);
            mma_bf16(S[j], qh, bh);
            mma_bf16(S[j], qh, bl);
            mma_bf16(S[j], ql, bh);
        }

        // ---- online softmax ----
        float cma = -1e30f, cmb = -1e30f;
        #pragma unroll
        for (int j = 0; j < 8; ++j) {
            cma = fmaxf(cma, fmaxf(S[j][0], S[j][1]));
            cmb = fmaxf(cmb, fmaxf(S[j][2], S[j][3]));
        }
        cma = fmaxf(cma, __shfl_xor_sync(0xffffffffu, cma, 1));
        cma = fmaxf(cma, __shfl_xor_sync(0xffffffffu, cma, 2));
        cmb = fmaxf(cmb, __shfl_xor_sync(0xffffffffu, cmb, 1));
        cmb = fmaxf(cmb, __shfl_xor_sync(0xffffffffu, cmb, 2));
        float Mna = fmaxf(Ma, cma), Mnb = fmaxf(Mb, cmb);
        float alA = __expf(Ma - Mna), alB = __expf(Mb - Mnb);
        Ma = Mna; Mb = Mnb;

        float sa = 0.f, sb = 0.f;
        #pragma unroll
        for (int j = 0; j < 8; ++j) {
            S[j][0] = __expf(S[j][0] - Ma); sa += S[j][0];
            S[j][1] = __expf(S[j][1] - Ma); sa += S[j][1];
            S[j][2] = __expf(S[j][2] - Mb); sb += S[j][2];
            S[j][3] = __expf(S[j][3] - Mb); sb += S[j][3];
        }
        sa += __shfl_xor_sync(0xffffffffu, sa, 1);
        sa += __shfl_xor_sync(0xffffffffu, sa, 2);
        sb += __shfl_xor_sync(0xffffffffu, sb, 1);
        sb += __shfl_xor_sync(0xffffffffu, sb, 2);
        la = la * alA + sa;
        lb = lb * alB + sb;
        #pragma unroll
        for (int cj = 0; cj < 8; ++cj) {
            z[cj][0] *= alA; z[cj][1] *= alA;
            z[cj][2] *= alB; z[cj][3] *= alB;
        }

        // ---- z += P @ v^T, 3-pass hi/lo; P frags direct from S regs ----
        #pragma unroll
        for (int ks = 0; ks < 4; ++ks) {
            uint4 ah = make_uint4(
                pack_bf16(S[2 * ks][0], S[2 * ks][1]),
                pack_bf16(S[2 * ks][2], S[2 * ks][3]),
                pack_bf16(S[2 * ks + 1][0], S[2 * ks + 1][1]),
                pack_bf16(S[2 * ks + 1][2], S[2 * ks + 1][3]));
            uint4 al = make_uint4(
                pack_bf16(bf16_lo(S[2 * ks][0]), bf16_lo(S[2 * ks][1])),
                pack_bf16(bf16_lo(S[2 * ks][2]), bf16_lo(S[2 * ks][3])),
                pack_bf16(bf16_lo(S[2 * ks + 1][0]), bf16_lo(S[2 * ks + 1][1])),
                pack_bf16(bf16_lo(S[2 * ks + 1][2]), bf16_lo(S[2 * ks + 1][3])));
            #pragma unroll
            for (int cj = 0; cj < 8; ++cj) {
                int c = cj * 8 + g;
                uint2 bh = make_uint2(vhi2[c * 36 + ks * 8 + tt],
                                      vhi2[c * 36 + ks * 8 + tt + 4]);
                uint2 bl = make_uint2(vlo2[c * 36 + ks * 8 + tt],
                                      vlo2[c * 36 + ks * 8 + tt + 4]);
                mma_bf16(z[cj], ah, bh);
                mma_bf16(z[cj], ah, bl);
                mma_bf16(z[cj], al, bh);
            }
        }
    }

    // ---- epilogue: normalize, z -> smem [c][128], then z_w 1x1 ----
    float lia = 1.f / la, lib = 1.f / lb;
    __syncthreads();
    #pragma unroll
    for (int cj = 0; cj < 8; ++cj) {
        int c = cj * 8 + 2 * tt;
        z_s[ c      * 128 + w * 16 + g    ] = z[cj][0] * lia;
        z_s[(c + 1) * 128 + w * 16 + g    ] = z[cj][1] * lia;
        z_s[ c      * 128 + w * 16 + g + 8] = z[cj][2] * lib;
        z_s[(c + 1) * 128 + w * 16 + g + 8] = z[cj][3] * lib;
    }
    for (int i = tid; i < 4096; i += 256) zw_s[i] = zw[i];
    __syncthreads();

    const int l = lane;
    float acc2[8][4];
    #pragma unroll
    for (int ci = 0; ci < 8; ++ci) {
        float bv = zb[w * 8 + ci];
        #pragma unroll
        for (int i = 0; i < 4; ++i) acc2[ci][i] = bv;
    }
    #pragma unroll 8
    for (int c = 0; c < 64; ++c) {
        float pv[4];
        #pragma unroll
        for (int i = 0; i < 4; ++i) pv[i] = z_s[c * 128 + l + 32 * i];
        #pragma unroll
        for (int ci = 0; ci < 8; ++ci) {
            float wv = zw_s[(w * 8 + ci) * 64 + c];
            #pragma unroll
            for (int i = 0; i < 4; ++i) acc2[ci][i] += wv * pv[i];
        }
    }
    #pragma unroll
    for (int ci = 0; ci < 8; ++ci) {
        int oc = w * 8 + ci;
        #pragma unroll
        for (int i = 0; i < 4; ++i) {
            int n = n0 + l + 32 * i;
            float val = acc2[ci][i];
            g_h[(b * 64 + oc) * 1024 + n] = val;
            out[((b * 64 + oc) * 16 + t) * 1024 + n] = val;
        }
    }
}

// ---------------- orchestration --------------------------------------------
extern "C" void kernel_launch(void* const* d_in, const int* in_sizes, int n_in,
                              void* d_out, int out_size)
{
    (void)in_sizes; (void)n_in; (void)out_size;
    const float* X   = (const float*)d_in[0];
    const float* Wc  = (const float*)d_in[1];
    const float* bcc = (const float*)d_in[2];
    const float* Wci = (const float*)d_in[3];
    const float* Wcf = (const float*)d_in[4];
    const float* Wco = (const float*)d_in[5];
    const float* qw  = (const float*)d_in[6];
    const float* qb  = (const float*)d_in[7];
    const float* kw  = (const float*)d_in[8];
    const float* kb  = (const float*)d_in[9];
    const float* vw  = (const float*)d_in[10];
    const float* vb  = (const float*)d_in[11];
    const float* zw  = (const float*)d_in[12];
    const float* zb  = (const float*)d_in[13];
    float* out = (float*)d_out;

    k_init <<<4096, 256>>>();
    k_prepw<<<1152, 256>>>(Wc);
    for (int t = 0; t < NT; ++t) {
        k_conv_mma<<<dim3(8, 16, 4),  256>>>(X, t);
        k_gate    <<<4096,            256>>>(bcc, Wci, Wcf, Wco);
        k_qkv     <<<dim3(4, 12, 16), 256>>>(qw, qb, kw, kb, vw, vb);
        k_flash   <<<dim3(8, 16),     256>>>(zw, zb, out, t);
    }
}

// round 11
// speedup vs baseline: 1.5212x; 1.0734x over previous
#include <cuda_runtime.h>
#include <cuda_bf16.h>
#include <math.h>
#include <cstdint>

#define BB 16
#define NT 16

// ---------------- persistent scratch (device globals; no allocation) -------
__device__ float g_h [16*64*1024];     // attended h (recurrent carry)
__device__ float g_hg[16*64*1024];     // pre-attention h (gate output)
__device__ float g_c [16*64*1024];     // cell state
__device__ float g_q [16*16*1024];
__device__ float g_conv[16*256*1024];  // conv output (B,256,32,32), pre-bias
// packed bf16x2 hi/lo k and v (written by k_qkv, read by k_flash)
__device__ uint32_t g_k2h[16*1024*8];  // [b][m][c2]   0.5 MB
__device__ uint32_t g_k2l[16*1024*8];
__device__ uint32_t g_v2h[16*64*512];  // [b][c][mp]   2 MB
__device__ uint32_t g_v2l[16*64*512];
// bf16 hi/lo split conv weights in mma-fragment-linear order
__device__ uint32_t g_Wfrag[294912];

// ---------------- init: zero h and c ---------------------------------------
__global__ void k_init()
{
    int i = blockIdx.x * 256 + threadIdx.x;
    g_h[i] = 0.f;
    g_c[i] = 0.f;
}

__device__ __forceinline__ float sigf(float x) { return 1.f / (1.f + __expf(-x)); }
__device__ __forceinline__ float tanh_fast(float x)
{
    return __fdividef(2.f, 1.f + __expf(-2.f * x)) - 1.f;
}
__device__ __forceinline__ uint32_t pack_bf16(float a, float b)
{
    __nv_bfloat162 h2 = __floats2bfloat162_rn(a, b);
    return *reinterpret_cast<uint32_t*>(&h2);
}
__device__ __forceinline__ float bf16_lo(float a)
{
    return a - __bfloat162float(__float2bfloat16(a));
}
__device__ __forceinline__ void mma_bf16(float* c, uint4 a, uint2 b)
{
    asm volatile(
        "mma.sync.aligned.m16n8k16.row.col.f32.bf16.bf16.f32 "
        "{%0,%1,%2,%3}, {%4,%5,%6,%7}, {%8,%9}, {%0,%1,%2,%3};"
        : "+f"(c[0]), "+f"(c[1]), "+f"(c[2]), "+f"(c[3])
        : "r"(a.x), "r"(a.y), "r"(a.z), "r"(a.w), "r"(b.x), "r"(b.y));
}

// ---------------- weight prep: split + fragment-linear layout --------------
__global__ void k_prepw(const float* __restrict__ Wc)
{
    int idx   = blockIdx.x * 256 + threadIdx.x;   // 294912
    int inner = idx & 4095;
    int outer = idx >> 12;
    int c0    = outer % 18;
    int gate  = outer / 18;
    int s     = inner & 1;
    int lane  = (inner >> 1) & 31;
    int ki    = (inner >> 6) & 3;
    int ni    = (inner >> 8) & 7;
    int sp    = (inner >> 11) & 1;

    int g = lane >> 2, tt = lane & 3;
    int n_global = gate * 64 + ni * 8 + g;
    int k0 = c0 * 64 + ki * 16 + 2 * tt + 8 * s;

    float w0, w1;
    {
        int ci = k0 / 9, r = k0 - ci * 9;
        w0 = Wc[(n_global * 128 + ci) * 9 + r];
        int k1 = k0 + 1;
        ci = k1 / 9; r = k1 - ci * 9;
        w1 = Wc[(n_global * 128 + ci) * 9 + r];
    }
    if (sp == 1) { w0 = bf16_lo(w0); w1 = bf16_lo(w1); }
    g_Wfrag[idx] = pack_bf16(w0, w1);
}

// ---------------- conv via mma.sync bf16 (R10 winner, unchanged) -----------
__global__ void __launch_bounds__(256, 2) k_conv_mma(
    const float* __restrict__ X, int t)
{
    __shared__ uint32_t sm_u[12288];       // 48 KB: Ah|Al|Bh|Bl
    uint32_t* Ah_s = sm_u;
    uint32_t* Al_s = sm_u + 4096;
    uint32_t* Bh_s = sm_u + 8192;
    uint32_t* Bl_s = sm_u + 10240;

    const int tid  = threadIdx.x;
    const int wid  = tid >> 5;
    const int lane = tid & 31;
    const int mt   = blockIdx.x;
    const int b    = blockIdx.y;
    const int gate = blockIdx.z;
    const int n0   = gate * 64;
    const int wm   = wid >> 1;
    const int wn   = wid & 1;
    const int g    = lane >> 2, tt = lane & 3;

    const float* Xb = X + (b * 64 * 16 + t) * 1024;
    const float* Hb = g_h + b * 64 * 1024;

    float acc[2][4][4];
    #pragma unroll
    for (int im = 0; im < 2; ++im)
        #pragma unroll
        for (int in = 0; in < 4; ++in)
            #pragma unroll
            for (int q = 0; q < 4; ++q) acc[im][in][q] = 0.f;

    const uint4* Ah4 = reinterpret_cast<const uint4*>(Ah_s);
    const uint4* Al4 = reinterpret_cast<const uint4*>(Al_s);
    const uint2* Bh2 = reinterpret_cast<const uint2*>(Bh_s);
    const uint2* Bl2 = reinterpret_cast<const uint2*>(Bl_s);

    for (int c0 = 0; c0 < 18; ++c0) {
        #pragma unroll
        for (int j = 0; j < 16; ++j) {
            int slot = j * 256 + tid;
            int s  = slot & 3;
            int ln = (slot >> 2) & 31;
            int ki = (slot >> 7) & 3;
            int mi = slot >> 9;
            int gg = ln >> 2, t4 = ln & 3;
            int m  = mi * 16 + gg + 8 * (s & 1);
            int kb = c0 * 64 + ki * 16 + 2 * t4 + 8 * (s >> 1);
            int pix = mt * 128 + m;
            int py = pix >> 5, px = pix & 31;
            float a0 = 0.f, a1 = 0.f;
            #pragma unroll
            for (int h = 0; h < 2; ++h) {
                int kg = kb + h;
                int ci = kg / 9, r = kg - ci * 9;
                int dy = r / 3 - 1, dx = r - (r / 3) * 3 - 1;
                int ys = py + dy, xs = px + dx;
                float a = 0.f;
                if ((unsigned)ys < 32u && (unsigned)xs < 32u) {
                    int sp2 = ys * 32 + xs;
                    a = (ci < 64) ? Xb[ci * 16384 + sp2]
                                  : Hb[(ci - 64) * 1024 + sp2];
                }
                if (h == 0) a0 = a; else a1 = a;
            }
            Ah_s[slot] = pack_bf16(a0, a1);
            Al_s[slot] = pack_bf16(bf16_lo(a0), bf16_lo(a1));
        }
        {
            const uint4* src = reinterpret_cast<const uint4*>(
                g_Wfrag + (gate * 18 + c0) * 4096);
            uint4* dh = reinterpret_cast<uint4*>(Bh_s);
            uint4* dl = reinterpret_cast<uint4*>(Bl_s);
            dh[tid]       = src[tid];
            dh[tid + 256] = src[tid + 256];
            dl[tid]       = src[tid + 512];
            dl[tid + 256] = src[tid + 768];
        }
        __syncthreads();

        #pragma unroll
        for (int ki = 0; ki < 4; ++ki) {
            uint4 a0h = Ah4[((wm * 2    ) * 4 + ki) * 32 + lane];
            uint4 a1h = Ah4[((wm * 2 + 1) * 4 + ki) * 32 + lane];
            uint4 a0l = Al4[((wm * 2    ) * 4 + ki) * 32 + lane];
            uint4 a1l = Al4[((wm * 2 + 1) * 4 + ki) * 32 + lane];
            #pragma unroll
            for (int in = 0; in < 4; ++in) {
                int ni = wn * 4 + in;
                uint2 bh = Bh2[(ni * 4 + ki) * 32 + lane];
                uint2 bl = Bl2[(ni * 4 + ki) * 32 + lane];
                mma_bf16(acc[0][in], a0h, bh);
                mma_bf16(acc[1][in], a1h, bh);
                mma_bf16(acc[0][in], a0h, bl);
                mma_bf16(acc[1][in], a1h, bl);
                mma_bf16(acc[0][in], a0l, bh);
                mma_bf16(acc[1][in], a1l, bh);
            }
        }
        __syncthreads();
    }

    float* out_s = reinterpret_cast<float*>(sm_u);
    #pragma unroll
    for (int im = 0; im < 2; ++im) {
        int mi = wm * 2 + im;
        int m  = mi * 16 + g;
        #pragma unroll
        for (int in = 0; in < 4; ++in) {
            int ni = wn * 4 + in;
            int n  = ni * 8 + 2 * tt;
            out_s[ n      * 132 + m    ] = acc[im][in][0];
            out_s[(n + 1) * 132 + m    ] = acc[im][in][1];
            out_s[ n      * 132 + m + 8] = acc[im][in][2];
            out_s[(n + 1) * 132 + m + 8] = acc[im][in][3];
        }
    }
    __syncthreads();
    #pragma unroll
    for (int j = 0; j < 32; ++j) {
        int idx = j * 256 + tid;
        int n = idx >> 7, m = idx & 127;
        g_conv[(b * 256 + n0 + n) * 1024 + mt * 128 + m] = out_s[n * 132 + m];
    }
}

// ---------------- ConvLSTM gating (elementwise) ----------------------------
__global__ void k_gate(const float* __restrict__ bc,
                       const float* __restrict__ Wci,
                       const float* __restrict__ Wcf,
                       const float* __restrict__ Wco)
{
    int idx = blockIdx.x * 256 + threadIdx.x;
    int b   = idx >> 16;
    int c   = (idx >> 10) & 63;
    int pos = idx & 1023;
    int cb  = (b * 256 + c) * 1024 + pos;

    float ic = g_conv[cb]              + bc[c];
    float fc = g_conv[cb + 64 * 1024]  + bc[64 + c];
    float gc = g_conv[cb + 128 * 1024] + bc[128 + c];
    float oc = g_conv[cb + 192 * 1024] + bc[192 + c];
    float cp = g_c[idx];
    int   wp = c * 1024 + pos;

    float i  = sigf(ic + Wci[wp] * cp);
    float f  = sigf(fc + Wcf[wp] * cp);
    float nc = f * cp + i * tanh_fast(gc);
    float o  = sigf(oc + Wco[wp] * nc);
    g_c[idx]  = nc;
    g_hg[idx] = o * tanh_fast(nc);
}

// ---------------- q,k,v 1x1 convs; k/v packed to bf16 hi/lo ---------------
__global__ void k_qkv(const float* __restrict__ qw, const float* __restrict__ qb,
                      const float* __restrict__ kw, const float* __restrict__ kb,
                      const float* __restrict__ vw, const float* __restrict__ vb)
{
    __shared__ float h_s[32 * 256];
    __shared__ float w_s[8 * 64];

    const int p0  = blockIdx.x * 256;
    const int oc0 = blockIdx.y * 8;
    const int b   = blockIdx.z;
    const int tid = threadIdx.x;

    for (int i = tid; i < 512; i += 256) {
        int j = i >> 6; int c = i & 63; int oc = oc0 + j;
        w_s[i] = (oc < 16) ? qw[oc * 64 + c]
               : (oc < 32) ? kw[(oc - 16) * 64 + c]
                           : vw[(oc - 32) * 64 + c];
    }

    float acc[8];
    #pragma unroll
    for (int j = 0; j < 8; ++j) {
        int oc = oc0 + j;
        acc[j] = (oc < 16) ? qb[oc] : (oc < 32) ? kb[oc - 16] : vb[oc - 32];
    }

    for (int chh = 0; chh < 2; ++chh) {
        __syncthreads();
        for (int i = tid; i < 8192; i += 256) {
            int c = i >> 8; int j = i & 255;
            h_s[i] = g_hg[(b * 64 + chh * 32 + c) * 1024 + p0 + j];
        }
        __syncthreads();
        #pragma unroll 8
        for (int c = 0; c < 32; ++c) {
            float hv = h_s[c * 256 + tid];
            #pragma unroll
            for (int j = 0; j < 8; ++j)
                acc[j] += w_s[j * 64 + chh * 32 + c] * hv;
        }
    }

    int pos = p0 + tid;
    if (oc0 < 16) {
        #pragma unroll
        for (int j = 0; j < 8; ++j)
            g_q[(b * 16 + oc0 + j) * 1024 + pos] = acc[j];
    } else if (oc0 < 32) {
        // k block: pack channel pairs (this thread owns 8 consecutive k ch)
        #pragma unroll
        for (int jj = 0; jj < 4; ++jj) {
            float k0 = acc[2 * jj], k1 = acc[2 * jj + 1];
            int c2 = ((oc0 - 16) >> 1) + jj;
            int o  = (b * 1024 + pos) * 8 + c2;
            g_k2h[o] = pack_bf16(k0, k1);
            g_k2l[o] = pack_bf16(bf16_lo(k0), bf16_lo(k1));
        }
    } else {
        // v block: pack position pairs via shfl with neighbor lane
        int vc0 = oc0 - 32;
        #pragma unroll
        for (int j = 0; j < 8; ++j) {
            float other = __shfl_xor_sync(0xffffffffu, acc[j], 1);
            if ((tid & 1) == 0) {
                int o = (b * 64 + vc0 + j) * 512 + (pos >> 1);
                g_v2h[o] = pack_bf16(acc[j], other);
                g_v2l[o] = pack_bf16(bf16_lo(acc[j]), bf16_lo(other));
            }
        }
    }
}

// ---------------- flash attention via mma, double-buffered staging ---------
// grid (8 n-tiles of 128 rows, 16 batch), 256 threads = 8 warps.
// Buffer layout (6144 u32 each, 2 buffers): khi[768 @0] klo[768 @768]
// vhi[2304 @1536] vlo[2304 @3840]. Strides 12/36 are bank-conflict-free.
__global__ void __launch_bounds__(256) k_flash(
    const float* __restrict__ zw, const float* __restrict__ zb,
    float* __restrict__ out, int t)
{
    __shared__ uint32_t pool[12288];               // 48 KB

    const int b    = blockIdx.y;
    const int n0   = blockIdx.x * 128;
    const int tid  = threadIdx.x;
    const int w    = tid >> 5;
    const int lane = tid & 31;
    const int g    = lane >> 2, tt = lane & 3;
    const int rA   = w * 16 + g;

    // ---- stage q tile into buf1 region, build frags, then it is dead ----
    float* q_s = reinterpret_cast<float*>(pool + 6144);   // [128][17]
    for (int i = tid; i < 2048; i += 256) {
        int c = i >> 7, r = i & 127;
        q_s[r * 17 + c] = g_q[(b * 16 + c) * 1024 + n0 + r];
    }
    __syncthreads();
    uint4 qh, ql;
    {
        float x0 = q_s[rA * 17 + 2 * tt],           x1 = q_s[rA * 17 + 2 * tt + 1];
        float x2 = q_s[(rA + 8) * 17 + 2 * tt],     x3 = q_s[(rA + 8) * 17 + 2 * tt + 1];
        float x4 = q_s[rA * 17 + 8 + 2 * tt],       x5 = q_s[rA * 17 + 9 + 2 * tt];
        float x6 = q_s[(rA + 8) * 17 + 8 + 2 * tt], x7 = q_s[(rA + 8) * 17 + 9 + 2 * tt];
        qh = make_uint4(pack_bf16(x0, x1), pack_bf16(x2, x3),
                        pack_bf16(x4, x5), pack_bf16(x6, x7));
        ql = make_uint4(pack_bf16(bf16_lo(x0), bf16_lo(x1)),
                        pack_bf16(bf16_lo(x2), bf16_lo(x3)),
                        pack_bf16(bf16_lo(x4), bf16_lo(x5)),
                        pack_bf16(bf16_lo(x6), bf16_lo(x7)));
    }

    uint32_t kh[2], kl[2], vh[8], vl[8];
    auto load_chunk = [&](int mc) {
        int kg = (b * 1024 + mc * 64) * 8;
        #pragma unroll
        for (int r = 0; r < 2; ++r) {
            kh[r] = g_k2h[kg + tid + r * 256];
            kl[r] = g_k2l[kg + tid + r * 256];
        }
        int vg = b * 64 * 512 + mc * 32;
        #pragma unroll
        for (int r = 0; r < 8; ++r) {
            int i = tid + r * 256;
            int c = i >> 5, mp = i & 31;
            vh[r] = g_v2h[vg + c * 512 + mp];
            vl[r] = g_v2l[vg + c * 512 + mp];
        }
    };
    auto store_chunk = [&](uint32_t* buf) {
        #pragma unroll
        for (int r = 0; r < 2; ++r) {
            int i = tid + r * 256;
            int m = i >> 3, c2 = i & 7;
            buf[m * 12 + c2]       = kh[r];
            buf[768 + m * 12 + c2] = kl[r];
        }
        #pragma unroll
        for (int r = 0; r < 8; ++r) {
            int i = tid + r * 256;
            int c = i >> 5, mp = i & 31;
            buf[1536 + c * 36 + mp] = vh[r];
            buf[3840 + c * 36 + mp] = vl[r];
        }
    };

    float z[8][4];
    #pragma unroll
    for (int cj = 0; cj < 8; ++cj)
        #pragma unroll
        for (int q = 0; q < 4; ++q) z[cj][q] = 0.f;
    float Ma = -1e30f, Mb = -1e30f, la = 0.f, lb = 0.f;

    // prologue: stage chunk 0 into buf0
    load_chunk(0);
    store_chunk(pool);
    __syncthreads();

    for (int mch = 0; mch < 16; ++mch) {
        uint32_t* cur = pool + (mch & 1) * 6144;
        uint32_t* nxt = pool + ((mch + 1) & 1) * 6144;
        if (mch < 15) load_chunk(mch + 1);   // LDGs hide under mma below

        // ---- S = q . k^T (128 x 64), 3-pass hi/lo ----
        float S[8][4];
        #pragma unroll
        for (int j = 0; j < 8; ++j)
            #pragma unroll
            for (int q = 0; q < 4; ++q) S[j][q] = 0.f;
        #pragma unroll
        for (int j = 0; j < 8; ++j) {
            int m = j * 8 + g;
            uint2 bh = make_uint2(cur[m * 12 + tt],       cur[m * 12 + tt + 4]);
            uint2 bl = make_uint2(cur[768 + m * 12 + tt], cur[768 + m * 12 + tt + 4]);
            mma_bf16(S[j], qh, bh);
            mma_bf16(S[j], qh, bl);
            mma_bf16(S[j], ql, bh);
        }

        // ---- online softmax ----
        float cma = -1e30f, cmb = -1e30f;
        #pragma unroll
        for (int j = 0; j < 8; ++j) {
            cma = fmaxf(cma, fmaxf(S[j][0], S[j][1]));
            cmb = fmaxf(cmb, fmaxf(S[j][2], S[j][3]));
        }
        cma = fmaxf(cma, __shfl_xor_sync(0xffffffffu, cma, 1));
        cma = fmaxf(cma, __shfl_xor_sync(0xffffffffu, cma, 2));
        cmb = fmaxf(cmb, __shfl_xor_sync(0xffffffffu, cmb, 1));
        cmb = fmaxf(cmb, __shfl_xor_sync(0xffffffffu, cmb, 2));
        float Mna = fmaxf(Ma, cma), Mnb = fmaxf(Mb, cmb);
        float alA = __expf(Ma - Mna), alB = __expf(Mb - Mnb);
        Ma = Mna; Mb = Mnb;

        float sa = 0.f, sb = 0.f;
        #pragma unroll
        for (int j = 0; j < 8; ++j) {
            S[j][0] = __expf(S[j][0] - Ma); sa += S[j][0];
            S[j][1] = __expf(S[j][1] - Ma); sa += S[j][1];
            S[j][2] = __expf(S[j][2] - Mb); sb += S[j][2];
            S[j][3] = __expf(S[j][3] - Mb); sb += S[j][3];
        }
        sa += __shfl_xor_sync(0xffffffffu, sa, 1);
        sa += __shfl_xor_sync(0xffffffffu, sa, 2);
        sb += __shfl_xor_sync(0xffffffffu, sb, 1);
        sb += __shfl_xor_sync(0xffffffffu, sb, 2);
        la = la * alA + sa;
        lb = lb * alB + sb;
        #pragma unroll
        for (int cj = 0; cj < 8; ++cj) {
            z[cj][0] *= alA; z[cj][1] *= alA;
            z[cj][2] *= alB; z[cj][3] *= alB;
        }

        // ---- z += P @ v^T, 3-pass hi/lo; P frags direct from S regs ----
        #pragma unroll
        for (int ks = 0; ks < 4; ++ks) {
            uint4 ah = make_uint4(
                pack_bf16(S[2 * ks][0], S[2 * ks][1]),
                pack_bf16(S[2 * ks][2], S[2 * ks][3]),
                pack_bf16(S[2 * ks + 1][0], S[2 * ks + 1][1]),
                pack_bf16(S[2 * ks + 1][2], S[2 * ks + 1][3]));
            uint4 al = make_uint4(
                pack_bf16(bf16_lo(S[2 * ks][0]), bf16_lo(S[2 * ks][1])),
                pack_bf16(bf16_lo(S[2 * ks][2]), bf16_lo(S[2 * ks][3])),
                pack_bf16(bf16_lo(S[2 * ks + 1][0]), bf16_lo(S[2 * ks + 1][1])),
                pack_bf16(bf16_lo(S[2 * ks + 1][2]), bf16_lo(S[2 * ks + 1][3])));
            #pragma unroll
            for (int cj = 0; cj < 8; ++cj) {
                int c = cj * 8 + g;
                uint2 bh = make_uint2(cur[1536 + c * 36 + ks * 8 + tt],
                                      cur[1536 + c * 36 + ks * 8 + tt + 4]);
                uint2 bl = make_uint2(cur[3840 + c * 36 + ks * 8 + tt],
                                      cur[3840 + c * 36 + ks * 8 + tt + 4]);
                mma_bf16(z[cj], ah, bh);
                mma_bf16(z[cj], ah, bl);
                mma_bf16(z[cj], al, bh);
            }
        }

        if (mch < 15) store_chunk(nxt);
        __syncthreads();
    }

    // ---- epilogue: normalize, z -> smem [c][128], then z_w 1x1 ----
    float* z_s  = reinterpret_cast<float*>(pool);          // [64][128]
    float* zw_s = reinterpret_cast<float*>(pool + 8192);   // 4096
    float lia = 1.f / la, lib = 1.f / lb;
    #pragma unroll
    for (int cj = 0; cj < 8; ++cj) {
        int c = cj * 8 + 2 * tt;
        z_s[ c      * 128 + w * 16 + g    ] = z[cj][0] * lia;
        z_s[(c + 1) * 128 + w * 16 + g    ] = z[cj][1] * lia;
        z_s[ c      * 128 + w * 16 + g + 8] = z[cj][2] * lib;
        z_s[(c + 1) * 128 + w * 16 + g + 8] = z[cj][3] * lib;
    }
    for (int i = tid; i < 4096; i += 256) zw_s[i] = zw[i];
    __syncthreads();

    const int l = lane;
    float acc2[8][4];
    #pragma unroll
    for (int ci = 0; ci < 8; ++ci) {
        float bv = zb[w * 8 + ci];
        #pragma unroll
        for (int i = 0; i < 4; ++i) acc2[ci][i] = bv;
    }
    #pragma unroll 8
    for (int c = 0; c < 64; ++c) {
        float pv[4];
        #pragma unroll
        for (int i = 0; i < 4; ++i) pv[i] = z_s[c * 128 + l + 32 * i];
        #pragma unroll
        for (int ci = 0; ci < 8; ++ci) {
            float wv = zw_s[(w * 8 + ci) * 64 + c];
            #pragma unroll
            for (int i = 0; i < 4; ++i) acc2[ci][i] += wv * pv[i];
        }
    }
    #pragma unroll
    for (int ci = 0; ci < 8; ++ci) {
        int oc = w * 8 + ci;
        #pragma unroll
        for (int i = 0; i < 4; ++i) {
            int n = n0 + l + 32 * i;
            float val = acc2[ci][i];
            g_h[(b * 64 + oc) * 1024 + n] = val;
            out[((b * 64 + oc) * 16 + t) * 1024 + n] = val;
        }
    }
}

// ---------------- orchestration --------------------------------------------
extern "C" void kernel_launch(void* const* d_in, const int* in_sizes, int n_in,
                              void* d_out, int out_size)
{
    (void)in_sizes; (void)n_in; (void)out_size;
    const float* X   = (const float*)d_in[0];
    const float* Wc  = (const float*)d_in[1];
    const float* bcc = (const float*)d_in[2];
    const float* Wci = (const float*)d_in[3];
    const float* Wcf = (const float*)d_in[4];
    const float* Wco = (const float*)d_in[5];
    const float* qw  = (const float*)d_in[6];
    const float* qb  = (const float*)d_in[7];
    const float* kw  = (const float*)d_in[8];
    const float* kb  = (const float*)d_in[9];
    const float* vw  = (const float*)d_in[10];
    const float* vb  = (const float*)d_in[11];
    const float* zw  = (const float*)d_in[12];
    const float* zb  = (const float*)d_in[13];
    float* out = (float*)d_out;

    k_init <<<4096, 256>>>();
    k_prepw<<<1152, 256>>>(Wc);
    for (int t = 0; t < NT; ++t) {
        k_conv_mma<<<dim3(8, 16, 4),  256>>>(X, t);
        k_gate    <<<4096,            256>>>(bcc, Wci, Wcf, Wco);
        k_qkv     <<<dim3(4, 12, 16), 256>>>(qw, qb, kw, kb, vw, vb);
        k_flash   <<<dim3(8, 16),     256>>>(zw, zb, out, t);
    }
}